// round 16
// baseline (speedup 1.0000x reference)
#include <cuda_runtime.h>
#include <cstdint>
#include <cstddef>

// Problem dims (fixed)
#define BB 4
#define KSEQ 4096
#define DD 2048
#define M_TOTAL (BB * KSEQ)   // 16384

// Scratch (__device__ globals). RULE: never cp.async FROM these (~40x slow);
// LDG/STG are full-speed.
__device__ float g_lam[(size_t)M_TOTAL * DD];     // 128 MB
// Per-(b, chunk128, channel) scan summaries, written by GEMM epilogue:
// P = prod(lam) over chunk, Q = chunk scan result from s0=0.
__device__ float g_P[(size_t)BB * 32 * DD];       // 1 MB
__device__ float g_Q[(size_t)BB * 32 * DD];       // 1 MB

// ---------------------------------------------------------------------------
// GEMM + bias + sigmoid via tf32 mma.sync m16n8k8 — R5 config (measured
// hardware floor ~155 TF/s legacy-mma): block 128x128x32, 256 thr (8 warps
// 2x4), warp 64x32, 3-stage cp.async, PAD=36 conflict-free scalar LDS.
// Epilogue also computes scan summaries (P,Q) for this (k-chunk,
// channel-tile) — the GEMM tile IS one scan task (128 consecutive k x 128
// channels). lam comes from registers via smem; u comes from x via LDG.
// BYTE-IDENTICAL to R15 (920us incl. epilogue; at the legacy-mma ceiling).
// ---------------------------------------------------------------------------
#define Bb 128
#define BN 128
#define BK 32
#define STAGES 3
#define PAD 36
#define A_ST_FLOATS (Bb * PAD)
#define B_ST_FLOATS (BN * PAD)
#define STAGE_FLOATS (A_ST_FLOATS + B_ST_FLOATS)
#define GEMM_SMEM (STAGES * STAGE_FLOATS * 4)     // 110592 B
#define GEMM_THREADS 256
#define TPAD 129                                  // epilogue tile row pitch

__device__ __forceinline__ uint32_t smem_u32(const void* p) {
    uint32_t a;
    asm("{ .reg .u64 t; cvta.to.shared.u64 t, %1; cvt.u32.u64 %0, t; }" : "=r"(a) : "l"(p));
    return a;
}
__device__ __forceinline__ void cpa16(uint32_t dst, const void* src) {
    asm volatile("cp.async.cg.shared.global [%0], [%1], 16;" :: "r"(dst), "l"(src) : "memory");
}
#define CP_COMMIT() asm volatile("cp.async.commit_group;" ::: "memory")
#define CP_WAIT(n)  asm volatile("cp.async.wait_group %0;" :: "n"(n) : "memory")

__device__ __forceinline__ uint32_t f32_to_tf32(float v) {
    uint32_t r;
    asm("cvt.rna.tf32.f32 %0, %1;" : "=r"(r) : "f"(v));
    return r;
}
__device__ __forceinline__ float sigmoidf_fast(float z) {
    return 1.0f / (1.0f + __expf(-z));
}

__global__ __launch_bounds__(GEMM_THREADS, 2)
void gemm_sigmoid_kernel(const float* __restrict__ A,      // x [M, D]
                         const float* __restrict__ W,      // W [E, D]
                         const float* __restrict__ bias) {
    extern __shared__ float smem[];
    const int tid  = threadIdx.x;
    const int warp = tid >> 5;
    const int lane = tid & 31;
    const int m0   = blockIdx.y * Bb;
    const int n0   = blockIdx.x * BN;
    const int wm   = (warp >> 2) * 64;
    const int wn   = (warp & 3) * 32;
    const int g    = lane >> 2;
    const int t4   = lane & 3;

    const int ldr = tid >> 3;
    const int lds = tid & 7;

    const uint32_t smem_base = smem_u32(smem);

    float acc[4][4][4];
#pragma unroll
    for (int i = 0; i < 4; i++)
#pragma unroll
        for (int j = 0; j < 4; j++)
#pragma unroll
            for (int c = 0; c < 4; c++) acc[i][j][c] = 0.0f;

    const int NKT = DD / BK;

    auto load_stage = [&](int kt, int s) {
        const int kk = kt * BK;
        const uint32_t sa = smem_base + (uint32_t)(s * STAGE_FLOATS) * 4u;
        const uint32_t sb = sa + (uint32_t)A_ST_FLOATS * 4u;
#pragma unroll
        for (int i = 0; i < 4; i++) {
            int row = i * 32 + ldr;
            cpa16(sa + (uint32_t)(row * PAD + lds * 4) * 4u,
                  A + (size_t)(m0 + row) * DD + kk + lds * 4);
        }
#pragma unroll
        for (int i = 0; i < 4; i++) {
            int row = i * 32 + ldr;
            cpa16(sb + (uint32_t)(row * PAD + lds * 4) * 4u,
                  W + (size_t)(n0 + row) * DD + kk + lds * 4);
        }
        CP_COMMIT();
    };

    load_stage(0, 0);
    load_stage(1, 1);

    for (int kt = 0; kt < NKT; kt++) {
        CP_WAIT(STAGES - 2);
        __syncthreads();

        const int s = kt % STAGES;
        const float* sA = smem + s * STAGE_FLOATS;
        const float* sB = sA + A_ST_FLOATS;

#pragma unroll
        for (int ks = 0; ks < BK; ks += 8) {
            uint32_t afr[4][4];
#pragma unroll
            for (int mt = 0; mt < 4; mt++) {
                const float* ap = sA + (wm + mt * 16 + g) * PAD + ks + t4;
                afr[mt][0] = f32_to_tf32(ap[0]);
                afr[mt][1] = f32_to_tf32(ap[8 * PAD]);
                afr[mt][2] = f32_to_tf32(ap[4]);
                afr[mt][3] = f32_to_tf32(ap[8 * PAD + 4]);
            }
            uint32_t bfr[4][2];
#pragma unroll
            for (int nt = 0; nt < 4; nt++) {
                const float* bp = sB + (wn + nt * 8 + g) * PAD + ks + t4;
                bfr[nt][0] = f32_to_tf32(bp[0]);
                bfr[nt][1] = f32_to_tf32(bp[4]);
            }
#pragma unroll
            for (int mt = 0; mt < 4; mt++) {
#pragma unroll
                for (int nt = 0; nt < 4; nt++) {
                    asm volatile(
                        "mma.sync.aligned.m16n8k8.row.col.f32.tf32.tf32.f32 "
                        "{%0,%1,%2,%3}, {%4,%5,%6,%7}, {%8,%9}, {%0,%1,%2,%3};"
                        : "+f"(acc[mt][nt][0]), "+f"(acc[mt][nt][1]),
                          "+f"(acc[mt][nt][2]), "+f"(acc[mt][nt][3])
                        : "r"(afr[mt][0]), "r"(afr[mt][1]),
                          "r"(afr[mt][2]), "r"(afr[mt][3]),
                          "r"(bfr[nt][0]), "r"(bfr[nt][1]));
                }
            }
        }
        __syncthreads();

        if (kt + STAGES - 1 < NKT)
            load_stage(kt + STAGES - 1, (kt + STAGES - 1) % STAGES);
        else
            CP_COMMIT();
    }

    // ---- epilogue 1: bias + sigmoid -> g_lam (gmem) + smem tile ----
    float* tile = smem;
#pragma unroll
    for (int mt = 0; mt < 4; mt++) {
#pragma unroll
        for (int half = 0; half < 2; half++) {
            const int row  = wm + mt * 16 + g + half * 8;   // local m-row
            float* dst = g_lam + (size_t)(m0 + row) * DD;
#pragma unroll
            for (int nt = 0; nt < 4; nt++) {
                const int col = wn + nt * 8 + t4 * 2;       // local channel
                float2 v;
                v.x = sigmoidf_fast(acc[mt][nt][2 * half + 0] + __ldg(bias + n0 + col));
                v.y = sigmoidf_fast(acc[mt][nt][2 * half + 1] + __ldg(bias + n0 + col + 1));
                *reinterpret_cast<float2*>(dst + n0 + col) = v;
                tile[row * TPAD + col]     = v.x;
                tile[row * TPAD + col + 1] = v.y;
            }
        }
    }
    __syncthreads();

    // ---- epilogue 2: per-channel scan summary (P,Q) for this 128-k chunk ----
    {
        const int e    = tid & 127;
        const int half = tid >> 7;
        const int b    = m0 >> 12;
        const int kcg  = (m0 >> 7) & 31;
        const int r0   = half * 64;

        float s = 0.0f, p = 1.0f;
#pragma unroll 8
        for (int j = 0; j < 64; j++) {
            float lm = tile[(r0 + j) * TPAD + e];
            float u  = __ldg(A + (size_t)(m0 + r0 + j) * DD + n0 + e);
            s = fmaf(lm, s - u, u);
            p *= lm;
        }
        float* ex = smem + 128 * TPAD;
        ex[(half * 128 + e) * 2 + 0] = p;
        ex[(half * 128 + e) * 2 + 1] = s;
        __syncthreads();
        if (half == 0) {
            float P0 = p, Q0 = s;
            float P1 = ex[(128 + e) * 2 + 0];
            float Q1 = ex[(128 + e) * 2 + 1];
            const size_t o = ((size_t)b * 32 + kcg) * DD + n0 + e;
            g_P[o] = P0 * P1;
            g_Q[o] = fmaf(P1, Q0, Q1);
        }
    }
}

// ---------------------------------------------------------------------------
// Single-pass scan, carry from precomputed (P,Q).
// Block: 32 channels (lane) x 32 chunk-warps (1024 thr).
// R16: carry-compose prologue batches P/Q loads 8-at-a-time (independent
// LDGs, fixed-bound predicated unroll — fits 64-reg cap) so the serial
// dependent chain is ~4 memory latencies instead of up to 31; replay loop
// unrolled x8 for MLP; streaming cache hints (x read-once, out write-once)
// preserve L2 for the lam tiles the GEMM just wrote.
// ---------------------------------------------------------------------------
#define SC_CHUNKS 32
#define SC_L (KSEQ / SC_CHUNKS)   // 128
__global__ __launch_bounds__(1024)
void scan_kernel(const float* __restrict__ x, float* __restrict__ out) {
    const int lane = threadIdx.x & 31;
    const int ck   = threadIdx.x >> 5;
    const int ch   = blockIdx.x * 32 + lane;
    const int b    = ch >> 11;
    const int d    = ch & (DD - 1);
    const size_t base = ((size_t)b * KSEQ + (size_t)ck * SC_L) * DD + d;

    // carry entering chunk ck: batched-prefetch compose
    float carry = 0.0f;
    {
        const float* Pp = g_P + (size_t)b * 32 * DD + d;
        const float* Qp = g_Q + (size_t)b * 32 * DD + d;
        int j = 0;
        while (j < ck) {
            const int n = ck - j;          // >=1
            float P[8], Q[8];
#pragma unroll
            for (int t = 0; t < 8; t++) {
                if (t < n) {
                    P[t] = __ldg(Pp + (size_t)(j + t) * DD);
                    Q[t] = __ldg(Qp + (size_t)(j + t) * DD);
                }
            }
#pragma unroll
            for (int t = 0; t < 8; t++)
                if (t < n) carry = fmaf(P[t], carry, Q[t]);
            j += (n < 8) ? n : 8;
        }
    }

    // replay with carry, write out (single gmem pass over lam/x)
    size_t idx = base;
    float ss = carry;
#pragma unroll 8
    for (int j = 0; j < SC_L; j++) {
        float lm = __ldg(g_lam + idx);
        float u  = __ldcs(x + idx);
        ss = fmaf(lm, ss - u, u);
        __stcs(out + idx, ss);
        idx += DD;
    }
}

// ---------------------------------------------------------------------------
extern "C" void kernel_launch(void* const* d_in, const int* in_sizes, int n_in,
                              void* d_out, int out_size) {
    const float* x    = (const float*)d_in[0];   // [B,K,D]
    const float* W    = (const float*)d_in[1];   // [D,D]
    const float* bias = (const float*)d_in[2];   // [D]
    float* out = (float*)d_out;                  // [B,K,D]

    cudaFuncSetAttribute(gemm_sigmoid_kernel,
                         cudaFuncAttributeMaxDynamicSharedMemorySize, GEMM_SMEM);

    dim3 ggrid(DD / BN, M_TOTAL / Bb);           // (16, 128)
    gemm_sigmoid_kernel<<<ggrid, GEMM_THREADS, GEMM_SMEM>>>(x, W, bias);

    scan_kernel<<<(BB * DD) / 32, 1024>>>(x, out);
}

// round 17
// speedup vs baseline: 1.1474x; 1.1474x over previous
#include <cuda_runtime.h>
#include <cstdint>
#include <cstddef>

// Problem dims (fixed)
#define BB 4
#define KSEQ 4096
#define DD 2048
#define M_TOTAL (BB * KSEQ)   // 16384

// Scratch (__device__ globals). RULE: never cp.async FROM these (~40x slow);
// LDG/STG are full-speed.
__device__ float g_lam[(size_t)M_TOTAL * DD];     // 128 MB
__device__ float g_P[(size_t)BB * 32 * DD];       // 1 MB
__device__ float g_Q[(size_t)BB * 32 * DD];       // 1 MB

// ---------------------------------------------------------------------------
// GEMM + bias + sigmoid via tf32 mma.sync m16n8k8. R15 skeleton (128x128x32,
// 256 thr, warp 64x32, 3-stage cp.async, PAD=36) with fragment loads via
// ldmatrix.x4 (6 LDSM replace 24 scalar LDS per ks-step; R7's ldmatrix test
// was invalidated by the scratch-cp.async pathology, never by ldmatrix).
// Epilogue computes lam + per-chunk scan summaries (P,Q) as in R15.
// ---------------------------------------------------------------------------
#define Bb 128
#define BN 128
#define BK 32
#define STAGES 3
#define PAD 36
#define A_ST_FLOATS (Bb * PAD)
#define B_ST_FLOATS (BN * PAD)
#define STAGE_FLOATS (A_ST_FLOATS + B_ST_FLOATS)
#define GEMM_SMEM (STAGES * STAGE_FLOATS * 4)     // 110592 B
#define GEMM_THREADS 256
#define TPAD 129

__device__ __forceinline__ uint32_t smem_u32(const void* p) {
    uint32_t a;
    asm("{ .reg .u64 t; cvta.to.shared.u64 t, %1; cvt.u32.u64 %0, t; }" : "=r"(a) : "l"(p));
    return a;
}
__device__ __forceinline__ void cpa16(uint32_t dst, const void* src) {
    asm volatile("cp.async.cg.shared.global [%0], [%1], 16;" :: "r"(dst), "l"(src) : "memory");
}
#define CP_COMMIT() asm volatile("cp.async.commit_group;" ::: "memory")
#define CP_WAIT(n)  asm volatile("cp.async.wait_group %0;" :: "n"(n) : "memory")

__device__ __forceinline__ void ldsm4(uint32_t* r, uint32_t addr) {
    asm volatile("ldmatrix.sync.aligned.m8n8.x4.shared.b16 {%0,%1,%2,%3}, [%4];"
                 : "=r"(r[0]), "=r"(r[1]), "=r"(r[2]), "=r"(r[3]) : "r"(addr));
}
__device__ __forceinline__ uint32_t f32_to_tf32(float v) {
    uint32_t r;
    asm("cvt.rna.tf32.f32 %0, %1;" : "=r"(r) : "f"(v));
    return r;
}
__device__ __forceinline__ float sigmoidf_fast(float z) {
    return 1.0f / (1.0f + __expf(-z));
}

__global__ __launch_bounds__(GEMM_THREADS, 2)
void gemm_sigmoid_kernel(const float* __restrict__ A,      // x [M, D]
                         const float* __restrict__ W,      // W [E, D]
                         const float* __restrict__ bias) {
    extern __shared__ float smem[];
    const int tid  = threadIdx.x;
    const int warp = tid >> 5;
    const int lane = tid & 31;
    const int m0   = blockIdx.y * Bb;
    const int n0   = blockIdx.x * BN;
    const int wm   = (warp >> 2) * 64;
    const int wn   = (warp & 3) * 32;
    const int g    = lane >> 2;
    const int t4   = lane & 3;

    // ldmatrix per-lane tile addressing
    const int lr   = lane & 7;             // row within 8-row tile
    const int ts   = lane >> 3;            // tile select 0..3
    const int aRow = (ts & 1) << 3;        // A: tile order m,m+8,k+4(m),k+4(m+8)
    const int aKof = (ts >> 1) << 2;
    const int bRow = (ts >> 1) << 3;       // B: tile order n,k+4(n),n+8,k+4(n+8)
    const int bKof = (ts & 1) << 2;

    const int ldr = tid >> 3;
    const int lds = tid & 7;

    const uint32_t smem_base = smem_u32(smem);
    // per-thread fragment byte offsets within a stage
    const uint32_t aOff = (uint32_t)((wm + lr + aRow) * PAD + aKof) * 4u;
    const uint32_t bOff = (uint32_t)(A_ST_FLOATS + (wn + lr + bRow) * PAD + bKof) * 4u;

    float acc[4][4][4];
#pragma unroll
    for (int i = 0; i < 4; i++)
#pragma unroll
        for (int j = 0; j < 4; j++)
#pragma unroll
            for (int c = 0; c < 4; c++) acc[i][j][c] = 0.0f;

    const int NKT = DD / BK;

    auto load_stage = [&](int kt, int s) {
        const int kk = kt * BK;
        const uint32_t sa = smem_base + (uint32_t)(s * STAGE_FLOATS) * 4u;
        const uint32_t sb = sa + (uint32_t)A_ST_FLOATS * 4u;
#pragma unroll
        for (int i = 0; i < 4; i++) {
            int row = i * 32 + ldr;
            cpa16(sa + (uint32_t)(row * PAD + lds * 4) * 4u,
                  A + (size_t)(m0 + row) * DD + kk + lds * 4);
        }
#pragma unroll
        for (int i = 0; i < 4; i++) {
            int row = i * 32 + ldr;
            cpa16(sb + (uint32_t)(row * PAD + lds * 4) * 4u,
                  W + (size_t)(n0 + row) * DD + kk + lds * 4);
        }
        CP_COMMIT();
    };

    load_stage(0, 0);
    load_stage(1, 1);

    for (int kt = 0; kt < NKT; kt++) {
        CP_WAIT(STAGES - 2);
        __syncthreads();

        const int s = kt % STAGES;
        const uint32_t stageB = smem_base + (uint32_t)(s * STAGE_FLOATS) * 4u;
        const uint32_t aB = stageB + aOff;
        const uint32_t bB = stageB + bOff;

#pragma unroll
        for (int ks = 0; ks < BK; ks += 8) {
            const uint32_t kOff = (uint32_t)ks * 4u;
            // A fragments: one ldsm.x4 per mt, then cvt to tf32 in-reg
            uint32_t afr[4][4];
#pragma unroll
            for (int mt = 0; mt < 4; mt++) {
                ldsm4(afr[mt], aB + (uint32_t)(mt * 16 * PAD) * 4u + kOff);
#pragma unroll
                for (int i = 0; i < 4; i++)
                    afr[mt][i] = f32_to_tf32(__uint_as_float(afr[mt][i]));
            }
            // B fragments: one ldsm.x4 per nt-pair
            uint32_t bfr[2][4];
#pragma unroll
            for (int np = 0; np < 2; np++) {
                ldsm4(bfr[np], bB + (uint32_t)(np * 16 * PAD) * 4u + kOff);
#pragma unroll
                for (int i = 0; i < 4; i++)
                    bfr[np][i] = f32_to_tf32(__uint_as_float(bfr[np][i]));
            }
#pragma unroll
            for (int mt = 0; mt < 4; mt++) {
#pragma unroll
                for (int nt = 0; nt < 4; nt++) {
                    const uint32_t* bp = &bfr[nt >> 1][(nt & 1) * 2];
                    asm volatile(
                        "mma.sync.aligned.m16n8k8.row.col.f32.tf32.tf32.f32 "
                        "{%0,%1,%2,%3}, {%4,%5,%6,%7}, {%8,%9}, {%0,%1,%2,%3};"
                        : "+f"(acc[mt][nt][0]), "+f"(acc[mt][nt][1]),
                          "+f"(acc[mt][nt][2]), "+f"(acc[mt][nt][3])
                        : "r"(afr[mt][0]), "r"(afr[mt][1]),
                          "r"(afr[mt][2]), "r"(afr[mt][3]),
                          "r"(bp[0]), "r"(bp[1]));
                }
            }
        }
        __syncthreads();

        if (kt + STAGES - 1 < NKT)
            load_stage(kt + STAGES - 1, (kt + STAGES - 1) % STAGES);
        else
            CP_COMMIT();
    }

    // ---- epilogue 1: bias + sigmoid -> g_lam (gmem) + smem tile ----
    float* tile = smem;
#pragma unroll
    for (int mt = 0; mt < 4; mt++) {
#pragma unroll
        for (int half = 0; half < 2; half++) {
            const int row  = wm + mt * 16 + g + half * 8;
            float* dst = g_lam + (size_t)(m0 + row) * DD;
#pragma unroll
            for (int nt = 0; nt < 4; nt++) {
                const int col = wn + nt * 8 + t4 * 2;
                float2 v;
                v.x = sigmoidf_fast(acc[mt][nt][2 * half + 0] + __ldg(bias + n0 + col));
                v.y = sigmoidf_fast(acc[mt][nt][2 * half + 1] + __ldg(bias + n0 + col + 1));
                *reinterpret_cast<float2*>(dst + n0 + col) = v;
                tile[row * TPAD + col]     = v.x;
                tile[row * TPAD + col + 1] = v.y;
            }
        }
    }
    __syncthreads();

    // ---- epilogue 2: per-channel scan summary (P,Q) for this 128-k chunk ----
    {
        const int e    = tid & 127;
        const int half = tid >> 7;
        const int b    = m0 >> 12;
        const int kcg  = (m0 >> 7) & 31;
        const int r0   = half * 64;

        float s = 0.0f, p = 1.0f;
#pragma unroll 8
        for (int j = 0; j < 64; j++) {
            float lm = tile[(r0 + j) * TPAD + e];
            float u  = __ldg(A + (size_t)(m0 + r0 + j) * DD + n0 + e);
            s = fmaf(lm, s - u, u);
            p *= lm;
        }
        float* ex = smem + 128 * TPAD;
        ex[(half * 128 + e) * 2 + 0] = p;
        ex[(half * 128 + e) * 2 + 1] = s;
        __syncthreads();
        if (half == 0) {
            float P0 = p, Q0 = s;
            float P1 = ex[(128 + e) * 2 + 0];
            float Q1 = ex[(128 + e) * 2 + 1];
            const size_t o = ((size_t)b * 32 + kcg) * DD + n0 + e;
            g_P[o] = P0 * P1;
            g_Q[o] = fmaf(P1, Q0, Q1);
        }
    }
}

// ---------------------------------------------------------------------------
// Single-pass scan, carry from precomputed (P,Q) — R15-exact (66.8us, at
// the 390MB traffic roofline; R16's "improvements" regressed it, reverted).
// ---------------------------------------------------------------------------
#define SC_CHUNKS 32
#define SC_L (KSEQ / SC_CHUNKS)   // 128
__global__ __launch_bounds__(1024)
void scan_kernel(const float* __restrict__ x, float* __restrict__ out) {
    const int lane = threadIdx.x & 31;
    const int ck   = threadIdx.x >> 5;
    const int ch   = blockIdx.x * 32 + lane;
    const int b    = ch >> 11;
    const int d    = ch & (DD - 1);
    const size_t base = ((size_t)b * KSEQ + (size_t)ck * SC_L) * DD + d;

    // carry entering chunk ck from published summaries
    float carry = 0.0f;
    {
        const float* Pp = g_P + (size_t)b * 32 * DD + d;
        const float* Qp = g_Q + (size_t)b * 32 * DD + d;
        for (int j = 0; j < ck; j++)
            carry = fmaf(__ldg(Pp + (size_t)j * DD), carry, __ldg(Qp + (size_t)j * DD));
    }

    // replay with carry, write out (single gmem pass over lam/x)
    size_t idx = base;
    float ss = carry;
#pragma unroll 4
    for (int j = 0; j < SC_L; j++) {
        float lm = __ldg(g_lam + idx);
        float u  = __ldg(x + idx);
        ss = fmaf(lm, ss - u, u);
        out[idx] = ss;
        idx += DD;
    }
}

// ---------------------------------------------------------------------------
extern "C" void kernel_launch(void* const* d_in, const int* in_sizes, int n_in,
                              void* d_out, int out_size) {
    const float* x    = (const float*)d_in[0];   // [B,K,D]
    const float* W    = (const float*)d_in[1];   // [D,D]
    const float* bias = (const float*)d_in[2];   // [D]
    float* out = (float*)d_out;                  // [B,K,D]

    cudaFuncSetAttribute(gemm_sigmoid_kernel,
                         cudaFuncAttributeMaxDynamicSharedMemorySize, GEMM_SMEM);

    dim3 ggrid(DD / BN, M_TOTAL / Bb);           // (16, 128)
    gemm_sigmoid_kernel<<<ggrid, GEMM_THREADS, GEMM_SMEM>>>(x, W, bias);

    scan_kernel<<<(BB * DD) / 32, 1024>>>(x, out);
}